// round 1
// baseline (speedup 1.0000x reference)
#include <cuda_runtime.h>

// SiLU(x) = x * sigmoid(x) = x / (1 + exp(-x))
// Pure streaming elementwise op: HBM-bound. float4 vectorized, 1 vec per thread.

__device__ __forceinline__ float silu1(float x) {
    // fast sigmoid via __expf (MUFU.EX2 path); rel err ~1e-6, threshold is 1e-3
    return x * (1.0f / (1.0f + __expf(-x)));
}

__global__ void __launch_bounds__(256) silu_kernel(const float4* __restrict__ in,
                                                   float4* __restrict__ out,
                                                   int n_vec) {
    int i = blockIdx.x * blockDim.x + threadIdx.x;
    if (i < n_vec) {
        float4 v = in[i];
        float4 r;
        r.x = silu1(v.x);
        r.y = silu1(v.y);
        r.z = silu1(v.z);
        r.w = silu1(v.w);
        out[i] = r;
    }
}

// Scalar tail fallback (not needed for this shape, kept for safety)
__global__ void silu_tail(const float* __restrict__ in, float* __restrict__ out,
                          int start, int n) {
    int i = start + blockIdx.x * blockDim.x + threadIdx.x;
    if (i < n) {
        float x = in[i];
        out[i] = x * (1.0f / (1.0f + __expf(-x)));
    }
}

extern "C" void kernel_launch(void* const* d_in, const int* in_sizes, int n_in,
                              void* d_out, int out_size) {
    const float* x = (const float*)d_in[0];
    float* y = (float*)d_out;
    int n = in_sizes[0];

    int n_vec = n / 4;
    int threads = 256;
    int blocks = (n_vec + threads - 1) / threads;
    silu_kernel<<<blocks, threads>>>((const float4*)x, (float4*)y, n_vec);

    int rem = n - n_vec * 4;
    if (rem > 0) {
        silu_tail<<<1, 256>>>(x, y, n_vec * 4, n);
    }
}

// round 2
// speedup vs baseline: 1.0621x; 1.0621x over previous
#include <cuda_runtime.h>

// SiLU(x) = x * sigmoid(x). HBM-bound streaming op.
// R2: 4x float4 per thread, loads batched up front (MLP_p1=4) to saturate HBM,
// streaming cache hints (.cs) since data has zero reuse.

__device__ __forceinline__ float silu1(float x) {
    return x * (1.0f / (1.0f + __expf(-x)));
}

__device__ __forceinline__ float4 silu4(float4 v) {
    float4 r;
    r.x = silu1(v.x);
    r.y = silu1(v.y);
    r.z = silu1(v.z);
    r.w = silu1(v.w);
    return r;
}

// Each thread handles 4 consecutive-strided float4 vectors.
// Layout: block covers a contiguous span of 4*256 vectors; thread t takes
// vectors {base + t, base + t + 256, base + t + 512, base + t + 768} so each
// of the 4 loads is fully coalesced across the warp.
__global__ void __launch_bounds__(256) silu_kernel_v4(const float4* __restrict__ in,
                                                      float4* __restrict__ out,
                                                      int n_vec) {
    int base = blockIdx.x * (blockDim.x * 4) + threadIdx.x;

    int i0 = base;
    int i1 = base + 256;
    int i2 = base + 512;
    int i3 = base + 768;

    if (i3 < n_vec) {
        // fast path: all four in-bounds, batched front loads
        float4 v0 = __ldcs(&in[i0]);
        float4 v1 = __ldcs(&in[i1]);
        float4 v2 = __ldcs(&in[i2]);
        float4 v3 = __ldcs(&in[i3]);
        __stcs(&out[i0], silu4(v0));
        __stcs(&out[i1], silu4(v1));
        __stcs(&out[i2], silu4(v2));
        __stcs(&out[i3], silu4(v3));
    } else {
        if (i0 < n_vec) __stcs(&out[i0], silu4(__ldcs(&in[i0])));
        if (i1 < n_vec) __stcs(&out[i1], silu4(__ldcs(&in[i1])));
        if (i2 < n_vec) __stcs(&out[i2], silu4(__ldcs(&in[i2])));
    }
}

// Scalar tail fallback (n not divisible by 4; not hit for this shape)
__global__ void silu_tail(const float* __restrict__ in, float* __restrict__ out,
                          int start, int n) {
    int i = start + blockIdx.x * blockDim.x + threadIdx.x;
    if (i < n) {
        float x = in[i];
        out[i] = x * (1.0f / (1.0f + __expf(-x)));
    }
}

extern "C" void kernel_launch(void* const* d_in, const int* in_sizes, int n_in,
                              void* d_out, int out_size) {
    const float* x = (const float*)d_in[0];
    float* y = (float*)d_out;
    int n = in_sizes[0];

    int n_vec = n / 4;
    const int threads = 256;
    const int vec_per_block = threads * 4;
    int blocks = (n_vec + vec_per_block - 1) / vec_per_block;
    silu_kernel_v4<<<blocks, threads>>>((const float4*)x, (float4*)y, n_vec);

    int rem = n - n_vec * 4;
    if (rem > 0) {
        silu_tail<<<1, 256>>>(x, y, n_vec * 4, n);
    }
}

// round 3
// speedup vs baseline: 1.0720x; 1.0093x over previous
#include <cuda_runtime.h>

// SiLU(x) = x * sigmoid(x). HBM-bound streaming op.
// R3: 8x float4 per thread (MLP_p1=8), predicate-free fast path for exact
// division, streaming cache hints (.cs) since data has zero reuse.

__device__ __forceinline__ float silu1(float x) {
    return x * (1.0f / (1.0f + __expf(-x)));
}

__device__ __forceinline__ float4 silu4(float4 v) {
    float4 r;
    r.x = silu1(v.x);
    r.y = silu1(v.y);
    r.z = silu1(v.z);
    r.w = silu1(v.w);
    return r;
}

#define VPT 8  // float4 vectors per thread

// Fast path: n_vec exactly divides grid coverage; no bounds checks.
// All 8 LDG.128 issued back-to-back at the top -> 8 outstanding lines/thread.
__global__ void __launch_bounds__(256) silu_kernel_v8_exact(const float4* __restrict__ in,
                                                            float4* __restrict__ out) {
    int base = blockIdx.x * (256 * VPT) + threadIdx.x;

    float4 v[VPT];
#pragma unroll
    for (int k = 0; k < VPT; k++)
        v[k] = __ldcs(&in[base + k * 256]);

#pragma unroll
    for (int k = 0; k < VPT; k++)
        __stcs(&out[base + k * 256], silu4(v[k]));
}

// Guarded fallback for arbitrary n_vec.
__global__ void __launch_bounds__(256) silu_kernel_v8_guard(const float4* __restrict__ in,
                                                            float4* __restrict__ out,
                                                            int n_vec) {
    int base = blockIdx.x * (256 * VPT) + threadIdx.x;
#pragma unroll
    for (int k = 0; k < VPT; k++) {
        int i = base + k * 256;
        if (i < n_vec) __stcs(&out[i], silu4(__ldcs(&in[i])));
    }
}

// Scalar tail (n not divisible by 4; not hit for this shape)
__global__ void silu_tail(const float* __restrict__ in, float* __restrict__ out,
                          int start, int n) {
    int i = start + blockIdx.x * blockDim.x + threadIdx.x;
    if (i < n) {
        float x = in[i];
        out[i] = x * (1.0f / (1.0f + __expf(-x)));
    }
}

extern "C" void kernel_launch(void* const* d_in, const int* in_sizes, int n_in,
                              void* d_out, int out_size) {
    const float* x = (const float*)d_in[0];
    float* y = (float*)d_out;
    int n = in_sizes[0];

    int n_vec = n / 4;
    const int threads = 256;
    const int vec_per_block = threads * VPT;

    if (n_vec % vec_per_block == 0) {
        int blocks = n_vec / vec_per_block;
        silu_kernel_v8_exact<<<blocks, threads>>>((const float4*)x, (float4*)y);
    } else {
        int blocks = (n_vec + vec_per_block - 1) / vec_per_block;
        silu_kernel_v8_guard<<<blocks, threads>>>((const float4*)x, (float4*)y, n_vec);
    }

    int rem = n - n_vec * 4;
    if (rem > 0) {
        silu_tail<<<1, 256>>>(x, y, n_vec * 4, n);
    }
}